// round 1
// baseline (speedup 1.0000x reference)
#include <cuda_runtime.h>
#include <math.h>

#define IN_DIM   2048
#define OUT_DIM  2048
#define RNK      4
#define LUTN     16
#define NORM_EPS 1e-6f
#define MAG_EPS  1e-6f

// ---------------- device scratch (no allocations allowed) ----------------
__device__ float d_nA[RNK];
__device__ float d_nB[RNK];
__device__ float d_g[RNK];
__device__ float d_Wt[(size_t)IN_DIM * OUT_DIM];   // Wt[i][o] = W[o][i], 16 MB

// ---------------- kernel 1: rank norms + softplus magnitudes ----------------
__global__ void prep_norms_kernel(const float* __restrict__ sA,
                                  const float* __restrict__ sB,
                                  const float* __restrict__ mag) {
    int w = threadIdx.x >> 5, lane = threadIdx.x & 31;
    int r = w & 3;
    float s = 0.f;
    if (w < 4) {
        for (int o = lane; o < OUT_DIM; o += 32) { float v = sA[o * RNK + r]; s += v * v; }
    } else {
        for (int i = lane; i < IN_DIM; i += 32) { float v = sB[r * IN_DIM + i]; s += v * v; }
    }
    #pragma unroll
    for (int off = 16; off; off >>= 1) s += __shfl_xor_sync(0xffffffffu, s, off);
    if (lane == 0) {
        float n = fmaxf(sqrtf(s), NORM_EPS);
        if (w < 4) d_nA[r] = n; else d_nB[r] = n;
    }
    if (threadIdx.x < RNK) {
        float m = mag[threadIdx.x];
        float sp = (m > 20.f) ? m : log1pf(expf(m));   // softplus, stable
        d_g[threadIdx.x] = sp + MAG_EPS;
    }
}

// ---------------- kernel 2: build Wt (dequant * rank-4 scale), transposed ----------------
__global__ void build_wt_kernel(const int* __restrict__ idx,
                                const float* __restrict__ lut,
                                const float* __restrict__ sA,
                                const float* __restrict__ sB) {
    __shared__ float tile[32][33];
    __shared__ float lutS[LUTN];
    __shared__ float cB[RNK][32];
    __shared__ float gOverNA[RNK];

    int i0 = blockIdx.x * 32, o0 = blockIdx.y * 32;
    int tx = threadIdx.x, ty = threadIdx.y;

    if (ty == 0 && tx < LUTN) lutS[tx] = lut[tx];
    if (ty == 1 && tx < RNK)  gOverNA[tx] = d_g[tx] / d_nA[tx];
    if (ty >= 4) {
        int r = ty - 4;
        cB[r][tx] = fabsf(sB[r * IN_DIM + i0 + tx]) / d_nB[r];
    }
    __syncthreads();

    #pragma unroll
    for (int oo = ty; oo < 32; oo += 8) {
        int o = o0 + oo;
        float c0 = fabsf(sA[o * RNK + 0]) * gOverNA[0];
        float c1 = fabsf(sA[o * RNK + 1]) * gOverNA[1];
        float c2 = fabsf(sA[o * RNK + 2]) * gOverNA[2];
        float c3 = fabsf(sA[o * RNK + 3]) * gOverNA[3];
        int id = idx[(size_t)o * IN_DIM + i0 + tx];
        float sc = c0 * cB[0][tx] + c1 * cB[1][tx] + c2 * cB[2][tx] + c3 * cB[3][tx];
        tile[oo][tx] = lutS[id] * sc;
    }
    __syncthreads();

    #pragma unroll
    for (int ii = ty; ii < 32; ii += 8) {
        d_Wt[(size_t)(i0 + ii) * OUT_DIM + o0 + tx] = tile[tx][ii];
    }
}

// ---------------- kernel 3: SGEMM y = x @ Wt + bias ----------------
// A = x [M, K=2048] row-major, B = Wt [K, N=2048] row-major, C [M, N].
#define BM 128
#define BN 128
#define BK 8
#define TM 8
#define TN 8

__global__ __launch_bounds__(256, 2)
void gemm_kernel(const float* __restrict__ A,
                 const float* __restrict__ bias,
                 float* __restrict__ C,
                 int M) {
    __shared__ float As[2][BK][BM];
    __shared__ float Bs[2][BK][BN];

    const int K = IN_DIM, N = OUT_DIM;
    int tid = threadIdx.x;
    int m0 = blockIdx.y * BM, n0 = blockIdx.x * BN;

    // A-tile loader mapping: 128 rows, 2 threads/row, float4 each
    int arow = tid >> 1, acol = (tid & 1) * 4;
    // B-tile loader mapping: 8 rows, 32 threads/row, float4 each
    int brow = tid >> 5, bcol = (tid & 31) * 4;

    const float* Aptr = A + (size_t)(m0 + arow) * K + acol;
    const float* Bptr = d_Wt + (size_t)brow * N + n0 + bcol;

    // first tile
    {
        float4 a4 = *(const float4*)(Aptr);
        As[0][acol + 0][arow] = a4.x;
        As[0][acol + 1][arow] = a4.y;
        As[0][acol + 2][arow] = a4.z;
        As[0][acol + 3][arow] = a4.w;
        float4 b4 = *(const float4*)(Bptr);
        *(float4*)&Bs[0][brow][bcol] = b4;
    }
    __syncthreads();

    int tx = tid & 15, ty = tid >> 4;  // 16 x 16 thread grid, 8x8 micro-tile
    float acc[TM][TN];
    #pragma unroll
    for (int i = 0; i < TM; i++)
        #pragma unroll
        for (int j = 0; j < TN; j++) acc[i][j] = 0.f;

    const int nk = K / BK;
    int cur = 0;
    for (int kt = 0; kt < nk; kt++) {
        float4 a4n, b4n;
        if (kt + 1 < nk) {
            a4n = *(const float4*)(Aptr + (kt + 1) * BK);
            b4n = *(const float4*)(Bptr + (size_t)(kt + 1) * BK * N);
        }
        #pragma unroll
        for (int k = 0; k < BK; k++) {
            float4 a0 = *(const float4*)&As[cur][k][ty * TM];
            float4 a1 = *(const float4*)&As[cur][k][ty * TM + 4];
            float4 b0 = *(const float4*)&Bs[cur][k][tx * TN];
            float4 b1 = *(const float4*)&Bs[cur][k][tx * TN + 4];
            float ar[TM] = {a0.x, a0.y, a0.z, a0.w, a1.x, a1.y, a1.z, a1.w};
            float br[TN] = {b0.x, b0.y, b0.z, b0.w, b1.x, b1.y, b1.z, b1.w};
            #pragma unroll
            for (int i = 0; i < TM; i++)
                #pragma unroll
                for (int j = 0; j < TN; j++)
                    acc[i][j] = fmaf(ar[i], br[j], acc[i][j]);
        }
        if (kt + 1 < nk) {
            int nxt = cur ^ 1;
            As[nxt][acol + 0][arow] = a4n.x;
            As[nxt][acol + 1][arow] = a4n.y;
            As[nxt][acol + 2][arow] = a4n.z;
            As[nxt][acol + 3][arow] = a4n.w;
            *(float4*)&Bs[nxt][brow][bcol] = b4n;
            __syncthreads();
            cur = nxt;
        }
    }

    // epilogue: + bias, store
    float bb[TN];
    #pragma unroll
    for (int j = 0; j < TN; j++) bb[j] = bias[n0 + tx * TN + j];

    #pragma unroll
    for (int i = 0; i < TM; i++) {
        int m = m0 + ty * TM + i;
        float* Crow = C + (size_t)m * N + n0 + tx * TN;
        float4 v0, v1;
        v0.x = acc[i][0] + bb[0]; v0.y = acc[i][1] + bb[1];
        v0.z = acc[i][2] + bb[2]; v0.w = acc[i][3] + bb[3];
        v1.x = acc[i][4] + bb[4]; v1.y = acc[i][5] + bb[5];
        v1.z = acc[i][6] + bb[6]; v1.w = acc[i][7] + bb[7];
        *(float4*)(Crow)     = v0;
        *(float4*)(Crow + 4) = v1;
    }
}

// ---------------- launch ----------------
extern "C" void kernel_launch(void* const* d_in, const int* in_sizes, int n_in,
                              void* d_out, int out_size) {
    const float* x       = (const float*)d_in[0];   // [B,S,IN] fp32
    const int*   indices = (const int*)d_in[1];     // [OUT,IN] int32
    const float* lut     = (const float*)d_in[2];   // [16]
    const float* sA      = (const float*)d_in[3];   // [OUT,R]
    const float* sB      = (const float*)d_in[4];   // [R,IN]
    const float* mag     = (const float*)d_in[5];   // [R]
    const float* bias    = (const float*)d_in[6];   // [OUT]
    float*       y       = (float*)d_out;           // [B,S,OUT] fp32

    int M = in_sizes[0] / IN_DIM;                   // 8192

    prep_norms_kernel<<<1, 256>>>(sA, sB, mag);
    build_wt_kernel<<<dim3(IN_DIM / 32, OUT_DIM / 32), dim3(32, 8)>>>(indices, lut, sA, sB);
    gemm_kernel<<<dim3(OUT_DIM / BN, M / BM), 256>>>(x, bias, y, M);
}

// round 3
// speedup vs baseline: 1.9475x; 1.9475x over previous
#include <cuda_runtime.h>
#include <cuda_bf16.h>
#include <math.h>
#include <stdint.h>

#define IN_DIM   2048
#define OUT_DIM  2048
#define RNK      4
#define LUTN     16
#define NORM_EPS 1e-6f
#define MAG_EPS  1e-6f

// GEMM config: K' = 6144 (seg0: xh*Wh, seg1: xl*Wh, seg2: xh*Wl)
#define KPACK   4096
#define NSTEP   192              // 6144 / 32
#define BK      32               // bf16 per k-step
#define STAGES  6
#define ROWB    80               // bytes per smem row (32 bf16 = 64B data, 80B stride: 5 coprime 8)
#define ATILE_BYTES (128 * ROWB) // 10240
#define STAGE_BYTES (2 * ATILE_BYTES)
#define SMEM_TOTAL  (STAGES * STAGE_BYTES)   // 122880

// ---------------- device scratch ----------------
__device__ float d_nA[RNK];
__device__ float d_nB[RNK];
__device__ float d_g[RNK];
__device__ __align__(1024) __nv_bfloat16 d_Abf[(size_t)8192 * KPACK];    // [M, 4096] hi|lo of x
__device__ __align__(1024) __nv_bfloat16 d_Bbf[(size_t)OUT_DIM * KPACK]; // [N, 4096] hi|lo of W

// ---------------- PTX helpers (plain sm_103-safe) ----------------
__device__ __forceinline__ uint32_t smem_u32(const void* p) {
    uint32_t a;
    asm("{ .reg .u64 t; cvta.to.shared.u64 t, %1; cvt.u32.u64 %0, t; }" : "=r"(a) : "l"(p));
    return a;
}
#define CP_ASYNC16(s, g) \
    asm volatile("cp.async.cg.shared.global [%0], [%1], 16;" :: "r"(s), "l"(g) : "memory")
#define CP_COMMIT() asm volatile("cp.async.commit_group;" ::: "memory")
#define CP_WAIT(N)  asm volatile("cp.async.wait_group %0;" :: "n"(N) : "memory")

__device__ __forceinline__ void ldm_x4(uint32_t& r0, uint32_t& r1, uint32_t& r2, uint32_t& r3,
                                       uint32_t addr) {
    asm volatile("ldmatrix.sync.aligned.m8n8.x4.shared.b16 {%0,%1,%2,%3}, [%4];"
                 : "=r"(r0), "=r"(r1), "=r"(r2), "=r"(r3) : "r"(addr));
}
__device__ __forceinline__ void mma_bf16(float& c0, float& c1, float& c2, float& c3,
                                         uint32_t a0, uint32_t a1, uint32_t a2, uint32_t a3,
                                         uint32_t b0, uint32_t b1) {
    asm volatile(
        "mma.sync.aligned.m16n8k16.row.col.f32.bf16.bf16.f32 "
        "{%0,%1,%2,%3}, {%4,%5,%6,%7}, {%8,%9}, {%0,%1,%2,%3};"
        : "+f"(c0), "+f"(c1), "+f"(c2), "+f"(c3)
        : "r"(a0), "r"(a1), "r"(a2), "r"(a3), "r"(b0), "r"(b1));
}

// ---------------- kernel 1: rank norms + softplus magnitudes ----------------
__global__ void prep_norms_kernel(const float* __restrict__ sA,
                                  const float* __restrict__ sB,
                                  const float* __restrict__ mag) {
    int w = threadIdx.x >> 5, lane = threadIdx.x & 31;
    int r = w & 3;
    float s = 0.f;
    if (w < 4) {
        for (int o = lane; o < OUT_DIM; o += 32) { float v = sA[o * RNK + r]; s += v * v; }
    } else {
        for (int i = lane; i < IN_DIM; i += 32) { float v = sB[r * IN_DIM + i]; s += v * v; }
    }
    #pragma unroll
    for (int off = 16; off; off >>= 1) s += __shfl_xor_sync(0xffffffffu, s, off);
    if (lane == 0) {
        float n = fmaxf(sqrtf(s), NORM_EPS);
        if (w < 4) d_nA[r] = n; else d_nB[r] = n;
    }
    if (threadIdx.x < RNK) {
        float m = mag[threadIdx.x];
        float sp = (m > 20.f) ? m : log1pf(expf(m));
        d_g[threadIdx.x] = sp + MAG_EPS;
    }
}

// ---------------- kernel 2: x -> bf16 hi/lo ----------------
__global__ void convert_x_kernel(const float* __restrict__ x) {
    size_t t = (size_t)blockIdx.x * blockDim.x + threadIdx.x;
    size_t base = t * 4;
    int m = (int)(base >> 11);
    int k = (int)(base & 2047);
    float4 v = *(const float4*)(x + base);
    float f[4] = {v.x, v.y, v.z, v.w};
    ushort hi[4], lo[4];
    #pragma unroll
    for (int j = 0; j < 4; j++) {
        __nv_bfloat16 h = __float2bfloat16(f[j]);
        __nv_bfloat16 l = __float2bfloat16(f[j] - __bfloat162float(h));
        hi[j] = __bfloat16_as_ushort(h);
        lo[j] = __bfloat16_as_ushort(l);
    }
    *(ushort4*)&d_Abf[(size_t)m * KPACK + k]        = make_ushort4(hi[0], hi[1], hi[2], hi[3]);
    *(ushort4*)&d_Abf[(size_t)m * KPACK + 2048 + k] = make_ushort4(lo[0], lo[1], lo[2], lo[3]);
}

// ---------------- kernel 3: build W -> bf16 hi/lo ----------------
__global__ void build_w_kernel(const int* __restrict__ idx,
                               const float* __restrict__ lut,
                               const float* __restrict__ sA,
                               const float* __restrict__ sB) {
    __shared__ float lutS[LUTN];
    if (threadIdx.x < LUTN) lutS[threadIdx.x] = lut[threadIdx.x];
    __syncthreads();

    size_t t = (size_t)blockIdx.x * blockDim.x + threadIdx.x;
    size_t base = t * 4;
    int o = (int)(base >> 11);
    int i0 = (int)(base & 2047);

    float cA[RNK];
    #pragma unroll
    for (int r = 0; r < RNK; r++)
        cA[r] = fabsf(sA[o * RNK + r]) * d_g[r] / (d_nA[r] * d_nB[r]);

    int4 id4 = *(const int4*)(idx + (size_t)o * IN_DIM + i0);
    int ids[4] = {id4.x, id4.y, id4.z, id4.w};
    ushort hi[4], lo[4];
    #pragma unroll
    for (int j = 0; j < 4; j++) {
        int i = i0 + j;
        float s = 0.f;
        #pragma unroll
        for (int r = 0; r < RNK; r++)
            s += cA[r] * fabsf(sB[r * IN_DIM + i]);
        float w = lutS[ids[j]] * s;
        __nv_bfloat16 h = __float2bfloat16(w);
        __nv_bfloat16 l = __float2bfloat16(w - __bfloat162float(h));
        hi[j] = __bfloat16_as_ushort(h);
        lo[j] = __bfloat16_as_ushort(l);
    }
    *(ushort4*)&d_Bbf[(size_t)o * KPACK + i0]        = make_ushort4(hi[0], hi[1], hi[2], hi[3]);
    *(ushort4*)&d_Bbf[(size_t)o * KPACK + 2048 + i0] = make_ushort4(lo[0], lo[1], lo[2], lo[3]);
}

// ---------------- kernel 4: mma.sync GEMM, CTA 128x128, K'=6144 ----------------
__global__ __launch_bounds__(256)
void gemm_kernel(const float* __restrict__ bias, float* __restrict__ y) {
    extern __shared__ char smem[];
    const uint32_t sbase = smem_u32(smem);

    const int tid = threadIdx.x, lane = tid & 31, wid = tid >> 5;
    const int warp_m = wid & 1, warp_n = wid >> 1;     // 2 x 4 warps, 64x32 warp tiles
    const int m0 = blockIdx.y * 128, n0 = blockIdx.x * 128;

    // loader mapping: thread covers chunks (r, c) and (r+64, c); r = tid>>2, c = tid&3
    const int lr = tid >> 2, lc = tid & 3;
    const __nv_bfloat16* Ag = d_Abf + (size_t)m0 * KPACK;
    const __nv_bfloat16* Bg = d_Bbf + (size_t)n0 * KPACK;

    // consumer per-lane smem offset components
    const uint32_t aLaneOff = (uint32_t)(lane & 15) * ROWB + (uint32_t)(lane >> 4) * 16;
    const uint32_t bLaneOff = (uint32_t)((lane & 7) + ((lane >> 4) << 3)) * ROWB
                            + (uint32_t)((lane >> 3) & 1) * 16;

    float acc[4][4][4];
    #pragma unroll
    for (int i = 0; i < 4; i++)
        #pragma unroll
        for (int j = 0; j < 4; j++)
            #pragma unroll
            for (int q = 0; q < 4; q++) acc[i][j][q] = 0.f;

    // ---- issue helper (inlined via macro-ish lambda) ----
    auto issue = [&](int t, int slot) {
        int kk  = (t & 63) << 5;
        int seg = t >> 6;
        int akk = kk + (seg == 1 ? 2048 : 0);
        int bkk = kk + (seg == 2 ? 2048 : 0);
        uint32_t sA = sbase + slot * STAGE_BYTES;
        uint32_t sB = sA + ATILE_BYTES;
        CP_ASYNC16(sA + lr * ROWB + lc * 16,
                   (const char*)(Ag + (size_t)lr * KPACK + akk + lc * 8));
        CP_ASYNC16(sA + (lr + 64) * ROWB + lc * 16,
                   (const char*)(Ag + (size_t)(lr + 64) * KPACK + akk + lc * 8));
        CP_ASYNC16(sB + lr * ROWB + lc * 16,
                   (const char*)(Bg + (size_t)lr * KPACK + bkk + lc * 8));
        CP_ASYNC16(sB + (lr + 64) * ROWB + lc * 16,
                   (const char*)(Bg + (size_t)(lr + 64) * KPACK + bkk + lc * 8));
    };

    // prologue: fill stages 0..4
    #pragma unroll
    for (int s = 0; s < STAGES - 1; s++) { issue(s, s); CP_COMMIT(); }
    CP_WAIT(4);
    __syncthreads();

    for (int t = 0; t < NSTEP; t++) {
        // refill the stage freed at iteration t-1
        if (t + STAGES - 1 < NSTEP) {
            issue(t + STAGES - 1, (t + STAGES - 1) % STAGES);
            CP_COMMIT();
        }

        // consume stage t
        {
            uint32_t sA = sbase + (t % STAGES) * STAGE_BYTES
                        + (uint32_t)(warp_m * 64) * ROWB + aLaneOff;
            uint32_t sB = sbase + (t % STAGES) * STAGE_BYTES + ATILE_BYTES
                        + (uint32_t)(warp_n * 32) * ROWB + bLaneOff;
            #pragma unroll
            for (int k16 = 0; k16 < 2; k16++) {
                uint32_t a[4][4], b[2][4];
                #pragma unroll
                for (int mi = 0; mi < 4; mi++)
                    ldm_x4(a[mi][0], a[mi][1], a[mi][2], a[mi][3],
                           sA + (uint32_t)(mi * 16) * ROWB + k16 * 32);
                #pragma unroll
                for (int p = 0; p < 2; p++)
                    ldm_x4(b[p][0], b[p][1], b[p][2], b[p][3],
                           sB + (uint32_t)(p * 16) * ROWB + k16 * 32);
                #pragma unroll
                for (int mi = 0; mi < 4; mi++)
                    #pragma unroll
                    for (int ni = 0; ni < 4; ni++) {
                        uint32_t b0 = b[ni >> 1][(ni & 1) * 2];
                        uint32_t b1 = b[ni >> 1][(ni & 1) * 2 + 1];
                        mma_bf16(acc[mi][ni][0], acc[mi][ni][1], acc[mi][ni][2], acc[mi][ni][3],
                                 a[mi][0], a[mi][1], a[mi][2], a[mi][3], b0, b1);
                    }
            }
        }

        if (t < NSTEP - STAGES + 1) { CP_WAIT(4); } else { CP_WAIT(0); }
        __syncthreads();
    }

    // ---- epilogue: + bias, float2 stores ----
    #pragma unroll
    for (int ni = 0; ni < 4; ni++) {
        int col = n0 + warp_n * 32 + ni * 8 + (lane & 3) * 2;
        float2 bb = *(const float2*)(bias + col);
        #pragma unroll
        for (int mi = 0; mi < 4; mi++) {
            int r0 = m0 + warp_m * 64 + mi * 16 + (lane >> 2);
            float2 v0, v1;
            v0.x = acc[mi][ni][0] + bb.x; v0.y = acc[mi][ni][1] + bb.y;
            v1.x = acc[mi][ni][2] + bb.x; v1.y = acc[mi][ni][3] + bb.y;
            *(float2*)(y + (size_t)r0 * OUT_DIM + col)       = v0;
            *(float2*)(y + (size_t)(r0 + 8) * OUT_DIM + col) = v1;
        }
    }
}

// ---------------- host ----------------
extern "C" void kernel_launch(void* const* d_in, const int* in_sizes, int n_in,
                              void* d_out, int out_size) {
    const float* x       = (const float*)d_in[0];
    const int*   indices = (const int*)d_in[1];
    const float* lut     = (const float*)d_in[2];
    const float* sA      = (const float*)d_in[3];
    const float* sB      = (const float*)d_in[4];
    const float* mag     = (const float*)d_in[5];
    const float* bias    = (const float*)d_in[6];
    float*       y       = (float*)d_out;

    int M = in_sizes[0] / IN_DIM;   // 8192

    cudaFuncSetAttribute(gemm_kernel, cudaFuncAttributeMaxDynamicSharedMemorySize, SMEM_TOTAL);

    prep_norms_kernel<<<1, 256>>>(sA, sB, mag);
    convert_x_kernel<<<(int)((size_t)M * IN_DIM / 4 / 256), 256>>>(x);
    build_w_kernel<<<(OUT_DIM * IN_DIM / 4) / 256, 256>>>(indices, lut, sA, sB);
    gemm_kernel<<<dim3(OUT_DIM / 128, M / 128), 256, SMEM_TOTAL>>>(bias, y);
}

// round 5
// speedup vs baseline: 2.4970x; 1.2822x over previous
#include <cuda_runtime.h>
#include <cuda_bf16.h>
#include <math.h>
#include <stdint.h>

#define IN_DIM   2048
#define OUT_DIM  2048
#define RNK      4
#define LUTN     16
#define NORM_EPS 1e-6f
#define MAG_EPS  1e-6f

// GEMM config: K' = 6144 (seg0: xh*Wh, seg1: xl*Wh, seg2: xh*Wl)
#define KPACK   4096
#define NSTEP   192              // 6144 / 32
#define STAGES  4
#define ROWB    80               // 32 bf16 = 64B data, 80B stride (5 coprime 8 -> conflict-free ldsm)
#define ATILE_BYTES (128 * ROWB) // 10240
#define STAGE_BYTES (2 * ATILE_BYTES)
#define SMEM_TOTAL  (STAGES * STAGE_BYTES)   // 81920 -> 2 CTAs/SM

// ---------------- device scratch ----------------
__device__ float d_nA[RNK];
__device__ float d_nB[RNK];
__device__ float d_g[RNK];
__device__ __align__(1024) __nv_bfloat16 d_Abf[(size_t)8192 * KPACK];    // [M, 4096] hi|lo of x
__device__ __align__(1024) __nv_bfloat16 d_Bbf[(size_t)OUT_DIM * KPACK]; // [N, 4096] hi|lo of W

// ---------------- PTX helpers (plain sm_103-safe) ----------------
__device__ __forceinline__ uint32_t smem_u32(const void* p) {
    uint32_t a;
    asm("{ .reg .u64 t; cvta.to.shared.u64 t, %1; cvt.u32.u64 %0, t; }" : "=r"(a) : "l"(p));
    return a;
}
#define CP_ASYNC16(s, g) \
    asm volatile("cp.async.cg.shared.global [%0], [%1], 16;" :: "r"(s), "l"(g) : "memory")
#define CP_COMMIT() asm volatile("cp.async.commit_group;" ::: "memory")
#define CP_WAIT(N)  asm volatile("cp.async.wait_group %0;" :: "n"(N) : "memory")

__device__ __forceinline__ void ldm_x4(uint32_t& r0, uint32_t& r1, uint32_t& r2, uint32_t& r3,
                                       uint32_t addr) {
    asm volatile("ldmatrix.sync.aligned.m8n8.x4.shared.b16 {%0,%1,%2,%3}, [%4];"
                 : "=r"(r0), "=r"(r1), "=r"(r2), "=r"(r3) : "r"(addr));
}
__device__ __forceinline__ void mma_bf16(float& c0, float& c1, float& c2, float& c3,
                                         uint32_t a0, uint32_t a1, uint32_t a2, uint32_t a3,
                                         uint32_t b0, uint32_t b1) {
    asm volatile(
        "mma.sync.aligned.m16n8k16.row.col.f32.bf16.bf16.f32 "
        "{%0,%1,%2,%3}, {%4,%5,%6,%7}, {%8,%9}, {%0,%1,%2,%3};"
        : "+f"(c0), "+f"(c1), "+f"(c2), "+f"(c3)
        : "r"(a0), "r"(a1), "r"(a2), "r"(a3), "r"(b0), "r"(b1));
}

// ---------------- kernel 1: rank norms + softplus magnitudes ----------------
__global__ void prep_norms_kernel(const float* __restrict__ sA,
                                  const float* __restrict__ sB,
                                  const float* __restrict__ mag) {
    int w = threadIdx.x >> 5, lane = threadIdx.x & 31;
    int r = w & 3;
    float s = 0.f;
    if (w < 4) {
        for (int o = lane; o < OUT_DIM; o += 32) { float v = sA[o * RNK + r]; s += v * v; }
    } else {
        for (int i = lane; i < IN_DIM; i += 32) { float v = sB[r * IN_DIM + i]; s += v * v; }
    }
    #pragma unroll
    for (int off = 16; off; off >>= 1) s += __shfl_xor_sync(0xffffffffu, s, off);
    if (lane == 0) {
        float n = fmaxf(sqrtf(s), NORM_EPS);
        if (w < 4) d_nA[r] = n; else d_nB[r] = n;
    }
    if (threadIdx.x < RNK) {
        float m = mag[threadIdx.x];
        float sp = (m > 20.f) ? m : log1pf(expf(m));
        d_g[threadIdx.x] = sp + MAG_EPS;
    }
}

// ---------------- kernel 2: x -> bf16 hi/lo ----------------
__global__ void convert_x_kernel(const float* __restrict__ x) {
    size_t t = (size_t)blockIdx.x * blockDim.x + threadIdx.x;
    size_t base = t * 4;
    int m = (int)(base >> 11);
    int k = (int)(base & 2047);
    float4 v = *(const float4*)(x + base);
    float f[4] = {v.x, v.y, v.z, v.w};
    ushort hi[4], lo[4];
    #pragma unroll
    for (int j = 0; j < 4; j++) {
        __nv_bfloat16 h = __float2bfloat16(f[j]);
        __nv_bfloat16 l = __float2bfloat16(f[j] - __bfloat162float(h));
        hi[j] = __bfloat16_as_ushort(h);
        lo[j] = __bfloat16_as_ushort(l);
    }
    *(ushort4*)&d_Abf[(size_t)m * KPACK + k]        = make_ushort4(hi[0], hi[1], hi[2], hi[3]);
    *(ushort4*)&d_Abf[(size_t)m * KPACK + 2048 + k] = make_ushort4(lo[0], lo[1], lo[2], lo[3]);
}

// ---------------- kernel 3: build W -> bf16 hi/lo ----------------
__global__ void build_w_kernel(const int* __restrict__ idx,
                               const float* __restrict__ lut,
                               const float* __restrict__ sA,
                               const float* __restrict__ sB) {
    __shared__ float lutS[LUTN];
    if (threadIdx.x < LUTN) lutS[threadIdx.x] = lut[threadIdx.x];
    __syncthreads();

    size_t t = (size_t)blockIdx.x * blockDim.x + threadIdx.x;
    size_t base = t * 4;
    int o = (int)(base >> 11);
    int i0 = (int)(base & 2047);

    float cA[RNK];
    #pragma unroll
    for (int r = 0; r < RNK; r++)
        cA[r] = fabsf(sA[o * RNK + r]) * d_g[r] / (d_nA[r] * d_nB[r]);

    int4 id4 = *(const int4*)(idx + (size_t)o * IN_DIM + i0);
    int ids[4] = {id4.x, id4.y, id4.z, id4.w};
    ushort hi[4], lo[4];
    #pragma unroll
    for (int j = 0; j < 4; j++) {
        int i = i0 + j;
        float s = 0.f;
        #pragma unroll
        for (int r = 0; r < RNK; r++)
            s += cA[r] * fabsf(sB[r * IN_DIM + i]);
        float w = lutS[ids[j]] * s;
        __nv_bfloat16 h = __float2bfloat16(w);
        __nv_bfloat16 l = __float2bfloat16(w - __bfloat162float(h));
        hi[j] = __bfloat16_as_ushort(h);
        lo[j] = __bfloat16_as_ushort(l);
    }
    *(ushort4*)&d_Bbf[(size_t)o * KPACK + i0]        = make_ushort4(hi[0], hi[1], hi[2], hi[3]);
    *(ushort4*)&d_Bbf[(size_t)o * KPACK + 2048 + i0] = make_ushort4(lo[0], lo[1], lo[2], lo[3]);
}

// ---------------- kernel 4: mma.sync GEMM, CTA 128x128, K'=6144, 2 CTAs/SM ----------------
__global__ __launch_bounds__(256, 2)
void gemm_kernel(const float* __restrict__ bias, float* __restrict__ y) {
    extern __shared__ char smem[];
    const uint32_t sbase = smem_u32(smem);

    const int tid = threadIdx.x, lane = tid & 31, wid = tid >> 5;
    const int warp_m = wid & 1, warp_n = wid >> 1;     // 2 x 4 warps, 64x32 warp tiles
    const int m0 = blockIdx.y * 128, n0 = blockIdx.x * 128;

    const int lr = tid >> 2, lc = tid & 3;
    const __nv_bfloat16* Ag = d_Abf + (size_t)m0 * KPACK;
    const __nv_bfloat16* Bg = d_Bbf + (size_t)n0 * KPACK;

    const uint32_t aLaneOff = (uint32_t)(lane & 15) * ROWB + (uint32_t)(lane >> 4) * 16;
    const uint32_t bLaneOff = (uint32_t)((lane & 7) + ((lane >> 4) << 3)) * ROWB
                            + (uint32_t)((lane >> 3) & 1) * 16;

    float acc[4][4][4];
    #pragma unroll
    for (int i = 0; i < 4; i++)
        #pragma unroll
        for (int j = 0; j < 4; j++)
            #pragma unroll
            for (int q = 0; q < 4; q++) acc[i][j][q] = 0.f;

    auto issue = [&](int t) {
        int slot = t & (STAGES - 1);
        int kk  = (t & 63) << 5;
        int seg = t >> 6;
        int akk = kk + (seg == 1 ? 2048 : 0);
        int bkk = kk + (seg == 2 ? 2048 : 0);
        uint32_t sA = sbase + slot * STAGE_BYTES;
        uint32_t sB = sA + ATILE_BYTES;
        CP_ASYNC16(sA + lr * ROWB + lc * 16,
                   (const char*)(Ag + (size_t)lr * KPACK + akk + lc * 8));
        CP_ASYNC16(sA + (lr + 64) * ROWB + lc * 16,
                   (const char*)(Ag + (size_t)(lr + 64) * KPACK + akk + lc * 8));
        CP_ASYNC16(sB + lr * ROWB + lc * 16,
                   (const char*)(Bg + (size_t)lr * KPACK + bkk + lc * 8));
        CP_ASYNC16(sB + (lr + 64) * ROWB + lc * 16,
                   (const char*)(Bg + (size_t)(lr + 64) * KPACK + bkk + lc * 8));
        CP_COMMIT();
    };

    // prologue: 3 stages in flight
    #pragma unroll
    for (int s = 0; s < STAGES - 1; s++) issue(s);

    for (int t = 0; t < NSTEP; t++) {
        // stage t becomes visible: <=2 groups still pending => group t complete
        if (t + STAGES - 1 < NSTEP) { CP_WAIT(2); } else { CP_WAIT(0); }
        __syncthreads();   // all warps see stage t; also protects slot reuse below

        // refill slot (t & 3) with chunk t+3 AFTER the barrier (slot t-1 was freed at this barrier)
        if (t + STAGES - 1 < NSTEP) issue(t + STAGES - 1);

        // consume stage t
        uint32_t sA = sbase + (t & (STAGES - 1)) * STAGE_BYTES
                    + (uint32_t)(warp_m * 64) * ROWB + aLaneOff;
        uint32_t sB = sbase + (t & (STAGES - 1)) * STAGE_BYTES + ATILE_BYTES
                    + (uint32_t)(warp_n * 32) * ROWB + bLaneOff;
        #pragma unroll
        for (int k16 = 0; k16 < 2; k16++) {
            uint32_t a[4][4], b[2][4];
            #pragma unroll
            for (int mi = 0; mi < 4; mi++)
                ldm_x4(a[mi][0], a[mi][1], a[mi][2], a[mi][3],
                       sA + (uint32_t)(mi * 16) * ROWB + k16 * 32);
            #pragma unroll
            for (int p = 0; p < 2; p++)
                ldm_x4(b[p][0], b[p][1], b[p][2], b[p][3],
                       sB + (uint32_t)(p * 16) * ROWB + k16 * 32);
            #pragma unroll
            for (int mi = 0; mi < 4; mi++)
                #pragma unroll
                for (int ni = 0; ni < 4; ni++) {
                    uint32_t b0 = b[ni >> 1][(ni & 1) * 2];
                    uint32_t b1 = b[ni >> 1][(ni & 1) * 2 + 1];
                    mma_bf16(acc[mi][ni][0], acc[mi][ni][1], acc[mi][ni][2], acc[mi][ni][3],
                             a[mi][0], a[mi][1], a[mi][2], a[mi][3], b0, b1);
                }
        }
        __syncthreads();   // consumption of slot t done before its next overwrite (t+4 issued at t+1)
    }

    // ---- epilogue: + bias, float2 stores ----
    #pragma unroll
    for (int ni = 0; ni < 4; ni++) {
        int col = n0 + warp_n * 32 + ni * 8 + (lane & 3) * 2;
        float2 bb = *(const float2*)(bias + col);
        #pragma unroll
        for (int mi = 0; mi < 4; mi++) {
            int r0 = m0 + warp_m * 64 + mi * 16 + (lane >> 2);
            float2 v0, v1;
            v0.x = acc[mi][ni][0] + bb.x; v0.y = acc[mi][ni][1] + bb.y;
            v1.x = acc[mi][ni][2] + bb.x; v1.y = acc[mi][ni][3] + bb.y;
            *(float2*)(y + (size_t)r0 * OUT_DIM + col)       = v0;
            *(float2*)(y + (size_t)(r0 + 8) * OUT_DIM + col) = v1;
        }
    }
}

// ---------------- host ----------------
extern "C" void kernel_launch(void* const* d_in, const int* in_sizes, int n_in,
                              void* d_out, int out_size) {
    const float* x       = (const float*)d_in[0];
    const int*   indices = (const int*)d_in[1];
    const float* lut     = (const float*)d_in[2];
    const float* sA      = (const float*)d_in[3];
    const float* sB      = (const float*)d_in[4];
    const float* mag     = (const float*)d_in[5];
    const float* bias    = (const float*)d_in[6];
    float*       y       = (float*)d_out;

    int M = in_sizes[0] / IN_DIM;   // 8192

    cudaFuncSetAttribute(gemm_kernel, cudaFuncAttributeMaxDynamicSharedMemorySize, SMEM_TOTAL);

    prep_norms_kernel<<<1, 256>>>(sA, sB, mag);
    convert_x_kernel<<<(int)((size_t)M * IN_DIM / 4 / 256), 256>>>(x);
    build_w_kernel<<<(OUT_DIM * IN_DIM / 4) / 256, 256>>>(indices, lut, sA, sB);
    gemm_kernel<<<dim3(OUT_DIM / 128, M / 128), 256, SMEM_TOTAL>>>(bias, y);
}

// round 6
// speedup vs baseline: 6.3492x; 2.5428x over previous
#include <cuda_runtime.h>
#include <cuda_bf16.h>
#include <cuda_fp16.h>
#include <math.h>
#include <stdint.h>

#define IN_DIM   2048
#define OUT_DIM  2048
#define RNK      4
#define LUTN     16
#define NORM_EPS 1e-6f
#define MAG_EPS  1e-6f

// GEMM config: single-pass fp16, K = 2048
#define NSTEP   64               // 2048 / 32
#define STAGES  4
#define ROWB    80               // 32 fp16 = 64B data, 80B stride (5 coprime 8 -> conflict-free ldsm)
#define ATILE_BYTES (128 * ROWB) // 10240
#define STAGE_BYTES (2 * ATILE_BYTES)
#define SMEM_TOTAL  (STAGES * STAGE_BYTES)   // 81920 -> 2 CTAs/SM

// ---------------- device scratch ----------------
__device__ float d_nA[RNK];
__device__ float d_nB[RNK];
__device__ float d_g[RNK];
__device__ __align__(1024) __half d_Ah[(size_t)8192 * IN_DIM];     // x as fp16 [M, 2048]
__device__ __align__(1024) __half d_Bh[(size_t)OUT_DIM * IN_DIM];  // W as fp16 [N, 2048]

// ---------------- PTX helpers (plain sm_103-safe) ----------------
__device__ __forceinline__ uint32_t smem_u32(const void* p) {
    uint32_t a;
    asm("{ .reg .u64 t; cvta.to.shared.u64 t, %1; cvt.u32.u64 %0, t; }" : "=r"(a) : "l"(p));
    return a;
}
#define CP_ASYNC16(s, g) \
    asm volatile("cp.async.cg.shared.global [%0], [%1], 16;" :: "r"(s), "l"(g) : "memory")
#define CP_COMMIT() asm volatile("cp.async.commit_group;" ::: "memory")
#define CP_WAIT(N)  asm volatile("cp.async.wait_group %0;" :: "n"(N) : "memory")

__device__ __forceinline__ void ldm_x4(uint32_t& r0, uint32_t& r1, uint32_t& r2, uint32_t& r3,
                                       uint32_t addr) {
    asm volatile("ldmatrix.sync.aligned.m8n8.x4.shared.b16 {%0,%1,%2,%3}, [%4];"
                 : "=r"(r0), "=r"(r1), "=r"(r2), "=r"(r3) : "r"(addr));
}
__device__ __forceinline__ void mma_f16(float& c0, float& c1, float& c2, float& c3,
                                        uint32_t a0, uint32_t a1, uint32_t a2, uint32_t a3,
                                        uint32_t b0, uint32_t b1) {
    asm volatile(
        "mma.sync.aligned.m16n8k16.row.col.f32.f16.f16.f32 "
        "{%0,%1,%2,%3}, {%4,%5,%6,%7}, {%8,%9}, {%0,%1,%2,%3};"
        : "+f"(c0), "+f"(c1), "+f"(c2), "+f"(c3)
        : "r"(a0), "r"(a1), "r"(a2), "r"(a3), "r"(b0), "r"(b1));
}

// ---------------- kernel 1: rank norms + softplus magnitudes ----------------
__global__ void prep_norms_kernel(const float* __restrict__ sA,
                                  const float* __restrict__ sB,
                                  const float* __restrict__ mag) {
    int w = threadIdx.x >> 5, lane = threadIdx.x & 31;
    int r = w & 3;
    float s = 0.f;
    if (w < 4) {
        for (int o = lane; o < OUT_DIM; o += 32) { float v = sA[o * RNK + r]; s += v * v; }
    } else {
        for (int i = lane; i < IN_DIM; i += 32) { float v = sB[r * IN_DIM + i]; s += v * v; }
    }
    #pragma unroll
    for (int off = 16; off; off >>= 1) s += __shfl_xor_sync(0xffffffffu, s, off);
    if (lane == 0) {
        float n = fmaxf(sqrtf(s), NORM_EPS);
        if (w < 4) d_nA[r] = n; else d_nB[r] = n;
    }
    if (threadIdx.x < RNK) {
        float m = mag[threadIdx.x];
        float sp = (m > 20.f) ? m : log1pf(expf(m));
        d_g[threadIdx.x] = sp + MAG_EPS;
    }
}

// ---------------- kernel 2: x -> fp16 ----------------
__global__ void convert_x_kernel(const float* __restrict__ x) {
    size_t t = (size_t)blockIdx.x * blockDim.x + threadIdx.x;
    size_t base = t * 4;
    float4 v = *(const float4*)(x + base);
    __half2 h0 = __floats2half2_rn(v.x, v.y);
    __half2 h1 = __floats2half2_rn(v.z, v.w);
    *(uint2*)&d_Ah[base] = make_uint2(*(uint32_t*)&h0, *(uint32_t*)&h1);
}

// ---------------- kernel 3: build W -> fp16 ----------------
__global__ void build_w_kernel(const int* __restrict__ idx,
                               const float* __restrict__ lut,
                               const float* __restrict__ sA,
                               const float* __restrict__ sB) {
    __shared__ float lutS[LUTN];
    if (threadIdx.x < LUTN) lutS[threadIdx.x] = lut[threadIdx.x];
    __syncthreads();

    size_t t = (size_t)blockIdx.x * blockDim.x + threadIdx.x;
    size_t base = t * 4;
    int o = (int)(base >> 11);
    int i0 = (int)(base & 2047);

    float cA[RNK];
    #pragma unroll
    for (int r = 0; r < RNK; r++)
        cA[r] = fabsf(sA[o * RNK + r]) * d_g[r] / (d_nA[r] * d_nB[r]);

    int4 id4 = *(const int4*)(idx + (size_t)o * IN_DIM + i0);
    int ids[4] = {id4.x, id4.y, id4.z, id4.w};
    float w[4];
    #pragma unroll
    for (int j = 0; j < 4; j++) {
        int i = i0 + j;
        float s = 0.f;
        #pragma unroll
        for (int r = 0; r < RNK; r++)
            s += cA[r] * fabsf(sB[r * IN_DIM + i]);
        w[j] = lutS[ids[j]] * s;
    }
    __half2 h0 = __floats2half2_rn(w[0], w[1]);
    __half2 h1 = __floats2half2_rn(w[2], w[3]);
    *(uint2*)&d_Bh[base] = make_uint2(*(uint32_t*)&h0, *(uint32_t*)&h1);
}

// ---------------- kernel 4: mma.sync fp16 GEMM, CTA 128x128, K=2048, 2 CTAs/SM ----------------
__global__ __launch_bounds__(256, 2)
void gemm_kernel(const float* __restrict__ bias, float* __restrict__ y) {
    extern __shared__ char smem[];
    const uint32_t sbase = smem_u32(smem);

    const int tid = threadIdx.x, lane = tid & 31, wid = tid >> 5;
    const int warp_m = wid & 1, warp_n = wid >> 1;     // 2 x 4 warps, 64x32 warp tiles
    const int m0 = blockIdx.y * 128, n0 = blockIdx.x * 128;

    const int lr = tid >> 2, lc = tid & 3;
    const __half* Ag = d_Ah + (size_t)m0 * IN_DIM;
    const __half* Bg = d_Bh + (size_t)n0 * IN_DIM;

    const uint32_t aLaneOff = (uint32_t)(lane & 15) * ROWB + (uint32_t)(lane >> 4) * 16;
    const uint32_t bLaneOff = (uint32_t)((lane & 7) + ((lane >> 4) << 3)) * ROWB
                            + (uint32_t)((lane >> 3) & 1) * 16;

    float acc[4][4][4];
    #pragma unroll
    for (int i = 0; i < 4; i++)
        #pragma unroll
        for (int j = 0; j < 4; j++)
            #pragma unroll
            for (int q = 0; q < 4; q++) acc[i][j][q] = 0.f;

    auto issue = [&](int t) {
        int slot = t & (STAGES - 1);
        int kk = t << 5;
        uint32_t sA = sbase + slot * STAGE_BYTES;
        uint32_t sB = sA + ATILE_BYTES;
        CP_ASYNC16(sA + lr * ROWB + lc * 16,
                   (const char*)(Ag + (size_t)lr * IN_DIM + kk + lc * 8));
        CP_ASYNC16(sA + (lr + 64) * ROWB + lc * 16,
                   (const char*)(Ag + (size_t)(lr + 64) * IN_DIM + kk + lc * 8));
        CP_ASYNC16(sB + lr * ROWB + lc * 16,
                   (const char*)(Bg + (size_t)lr * IN_DIM + kk + lc * 8));
        CP_ASYNC16(sB + (lr + 64) * ROWB + lc * 16,
                   (const char*)(Bg + (size_t)(lr + 64) * IN_DIM + kk + lc * 8));
        CP_COMMIT();
    };

    // prologue: 3 stages in flight
    #pragma unroll
    for (int s = 0; s < STAGES - 1; s++) issue(s);

    for (int t = 0; t < NSTEP; t++) {
        if (t + STAGES - 1 < NSTEP) { CP_WAIT(2); } else { CP_WAIT(0); }
        __syncthreads();

        if (t + STAGES - 1 < NSTEP) issue(t + STAGES - 1);

        uint32_t sA = sbase + (t & (STAGES - 1)) * STAGE_BYTES
                    + (uint32_t)(warp_m * 64) * ROWB + aLaneOff;
        uint32_t sB = sbase + (t & (STAGES - 1)) * STAGE_BYTES + ATILE_BYTES
                    + (uint32_t)(warp_n * 32) * ROWB + bLaneOff;
        #pragma unroll
        for (int k16 = 0; k16 < 2; k16++) {
            uint32_t a[4][4], b[2][4];
            #pragma unroll
            for (int mi = 0; mi < 4; mi++)
                ldm_x4(a[mi][0], a[mi][1], a[mi][2], a[mi][3],
                       sA + (uint32_t)(mi * 16) * ROWB + k16 * 32);
            #pragma unroll
            for (int p = 0; p < 2; p++)
                ldm_x4(b[p][0], b[p][1], b[p][2], b[p][3],
                       sB + (uint32_t)(p * 16) * ROWB + k16 * 32);
            #pragma unroll
            for (int mi = 0; mi < 4; mi++)
                #pragma unroll
                for (int ni = 0; ni < 4; ni++) {
                    uint32_t b0 = b[ni >> 1][(ni & 1) * 2];
                    uint32_t b1 = b[ni >> 1][(ni & 1) * 2 + 1];
                    mma_f16(acc[mi][ni][0], acc[mi][ni][1], acc[mi][ni][2], acc[mi][ni][3],
                            a[mi][0], a[mi][1], a[mi][2], a[mi][3], b0, b1);
                }
        }
        __syncthreads();
    }

    // ---- epilogue: + bias, float2 stores ----
    #pragma unroll
    for (int ni = 0; ni < 4; ni++) {
        int col = n0 + warp_n * 32 + ni * 8 + (lane & 3) * 2;
        float2 bb = *(const float2*)(bias + col);
        #pragma unroll
        for (int mi = 0; mi < 4; mi++) {
            int r0 = m0 + warp_m * 64 + mi * 16 + (lane >> 2);
            float2 v0, v1;
            v0.x = acc[mi][ni][0] + bb.x; v0.y = acc[mi][ni][1] + bb.y;
            v1.x = acc[mi][ni][2] + bb.x; v1.y = acc[mi][ni][3] + bb.y;
            *(float2*)(y + (size_t)r0 * OUT_DIM + col)       = v0;
            *(float2*)(y + (size_t)(r0 + 8) * OUT_DIM + col) = v1;
        }
    }
}

// ---------------- host ----------------
extern "C" void kernel_launch(void* const* d_in, const int* in_sizes, int n_in,
                              void* d_out, int out_size) {
    const float* x       = (const float*)d_in[0];
    const int*   indices = (const int*)d_in[1];
    const float* lut     = (const float*)d_in[2];
    const float* sA      = (const float*)d_in[3];
    const float* sB      = (const float*)d_in[4];
    const float* mag     = (const float*)d_in[5];
    const float* bias    = (const float*)d_in[6];
    float*       y       = (float*)d_out;

    int M = in_sizes[0] / IN_DIM;   // 8192

    cudaFuncSetAttribute(gemm_kernel, cudaFuncAttributeMaxDynamicSharedMemorySize, SMEM_TOTAL);

    prep_norms_kernel<<<1, 256>>>(sA, sB, mag);
    convert_x_kernel<<<(int)((size_t)M * IN_DIM / 4 / 256), 256>>>(x);
    build_w_kernel<<<(OUT_DIM * IN_DIM / 4) / 256, 256>>>(indices, lut, sA, sB);
    gemm_kernel<<<dim3(OUT_DIM / 128, M / 128), 256, SMEM_TOTAL>>>(bias, y);
}